// round 9
// baseline (speedup 1.0000x reference)
#include <cuda_runtime.h>
#include <cstdint>

// Fixed problem shapes
#define BB 4
#define HH 224
#define WW 224
#define CC 16
#define FF 32
#define HO 220
#define WO 220
#define WG 56          // 56 four-col groups cover a 224-wide row (last group pad)
#define VP 236         // padded V row stride (words): 16B-aligned rows, 2-way STS max
#define R4P 57         // padded R4 row stride: conflict-free STS

#define MAGIC_I 0x4B400000
#define MAGIC_F 12582912.0f

__device__ __forceinline__ int dp4a_us(unsigned a, unsigned b, int c) {
    int d;
    asm("dp4a.u32.s32 %0, %1, %2, %3;" : "=r"(d) : "r"(a), "r"(b), "r"(c));
    return d;
}

// Exact u8 extraction from an integer-valued float in [0,255]:
// f + 2^23 puts the value in the low mantissa bits; byte0 == value.
__device__ __forceinline__ unsigned f2b(float f) {
    return __float_as_uint(f + 8388608.0f);
}

// One float4 output group: cols 4g..4g+3, vertical words A (4g..4g+3) and
// B (4g+4..4g+7) covering input rows ho..ho+3; ra/rb horizontal row ho+4.
__device__ __forceinline__ void conv_group(
    uint4 A, uint4 B, unsigned ra, unsigned rb,
    unsigned Kv0, unsigned Kv1, unsigned Kv2, unsigned Kv3, unsigned Kv4,
    unsigned lo0, unsigned lo1, unsigned lo2, unsigned lo3,
    unsigned hi0, unsigned hi1, unsigned hi2, unsigned hi3,
    float* dst)
{
    int a0 = dp4a_us(A.x, Kv0, MAGIC_I);
    a0 = dp4a_us(A.y, Kv1, a0);
    a0 = dp4a_us(A.z, Kv2, a0);
    a0 = dp4a_us(A.w, Kv3, a0);
    a0 = dp4a_us(B.x, Kv4, a0);
    a0 = dp4a_us(ra, lo0, a0);
    a0 = dp4a_us(rb, hi0, a0);

    int a1 = dp4a_us(A.y, Kv0, MAGIC_I);
    a1 = dp4a_us(A.z, Kv1, a1);
    a1 = dp4a_us(A.w, Kv2, a1);
    a1 = dp4a_us(B.x, Kv3, a1);
    a1 = dp4a_us(B.y, Kv4, a1);
    a1 = dp4a_us(ra, lo1, a1);
    a1 = dp4a_us(rb, hi1, a1);

    int a2 = dp4a_us(A.z, Kv0, MAGIC_I);
    a2 = dp4a_us(A.w, Kv1, a2);
    a2 = dp4a_us(B.x, Kv2, a2);
    a2 = dp4a_us(B.y, Kv3, a2);
    a2 = dp4a_us(B.z, Kv4, a2);
    a2 = dp4a_us(ra, lo2, a2);
    a2 = dp4a_us(rb, hi2, a2);

    int a3 = dp4a_us(A.w, Kv0, MAGIC_I);
    a3 = dp4a_us(B.x, Kv1, a3);
    a3 = dp4a_us(B.y, Kv2, a3);
    a3 = dp4a_us(B.z, Kv3, a3);
    a3 = dp4a_us(B.w, Kv4, a3);
    a3 = dp4a_us(ra, lo3, a3);
    a3 = dp4a_us(rb, hi3, a3);

    float4 o = make_float4(__int_as_float(a0) - MAGIC_F,
                           __int_as_float(a1) - MAGIC_F,
                           __int_as_float(a2) - MAGIC_F,
                           __int_as_float(a3) - MAGIC_F);
    *(float4*)dst = o;
}

// -------------------------------------------------------------------------
// Single fused kernel. grid = B*HO (880). 512 threads = 16 warps = channels.
// Staging converts NHWC fp32 rows ho..ho+4 directly:
//   Vsm[c][w] = u8x4(rows ho..ho+3 at col w)   (vertical packing, 5 dp4a taps)
//   R4sm[c][g] = u8x4(row ho+4, cols 4g..4g+3) (horizontal, 2 dp4a taps)
// Main loop: lane handles TWO adjacent float4 groups (g=2*lane, 2*lane+1)
// sharing the middle uint4, so 7 weight LDS + 6 shifts amortize over 8 outputs.
// Stores: each lane writes 32 contiguous bytes -> fully coalesced STG.128 x2.
// -------------------------------------------------------------------------
__global__ __launch_bounds__(512, 2) void conv_fused_kernel(
    const float* __restrict__ in, const float* __restrict__ kern,
    float* __restrict__ out)
{
    __shared__ __align__(16) unsigned Vsm[CC][VP];    // 15104 B
    __shared__ unsigned R4sm[CC][R4P];                // 3648 B
    __shared__ unsigned Wsm[7][CC * FF];              // 14336 B  (33088 total)

    int bid = blockIdx.x;
    int ho = bid % HO;
    int b = bid / HO;
    int tid = threadIdx.x;
    int c = tid >> 5;
    int lane = tid & 31;

    // ---- Pack weights: thread = pair (c,f) = tid; fully coalesced reads ----
    {
        int kk[25];
#pragma unroll
        for (int t = 0; t < 25; t++)
            kk[t] = (int)kern[t * (CC * FF) + tid];   // ((i*5+j)*CC+c)*FF+f
#pragma unroll
        for (int j = 0; j < 5; j++)
            Wsm[j][tid] = ((unsigned)(kk[j] & 0xFF))
                        | ((unsigned)(kk[5 + j] & 0xFF) << 8)
                        | ((unsigned)(kk[10 + j] & 0xFF) << 16)
                        | ((unsigned)(kk[15 + j] & 0xFF) << 24);
        Wsm[5][tid] = ((unsigned)(kk[20] & 0xFF))
                    | ((unsigned)(kk[21] & 0xFF) << 8)
                    | ((unsigned)(kk[22] & 0xFF) << 16)
                    | ((unsigned)(kk[23] & 0xFF) << 24);
        Wsm[6][tid] = (unsigned)(kk[24] & 0xFF);
    }

    // ---- Stage input rows ho..ho+4 straight from NHWC fp32 ----
    const float* rin = in + (size_t)(b * HH + ho) * WW * CC;

    // Vertical words: idx -> (cc = idx&15, w = idx>>4); lane-consecutive cc
    // means consecutive floats -> perfectly coalesced 128B reads per row.
#pragma unroll
    for (int p = 0; p < 7; p++) {
        int idx = tid + p * 512;                 // 7*512 = 3584 = CC*WW exactly
        int cc = idx & 15, w = idx >> 4;
        const float* q = rin + w * CC + cc;
        unsigned u0 = f2b(q[0]);
        unsigned u1 = f2b(q[WW * CC]);
        unsigned u2 = f2b(q[2 * WW * CC]);
        unsigned u3 = f2b(q[3 * WW * CC]);
        unsigned r = __byte_perm(u0, u1, 0x0040); // b0=u0.b0, b1=u1.b0
        r = __byte_perm(r, u2, 0x0410);           // b2=u2.b0
        r = __byte_perm(r, u3, 0x4210);           // b3=u3.b0
        Vsm[cc][w] = r;
    }
    // Row ho+4 horizontal words (896 of them)
#pragma unroll
    for (int p = 0; p < 2; p++) {
        int idx = tid + p * 512;
        if (idx < CC * WG) {
            int cc = idx & 15, g = idx >> 4;
            const float* q = rin + 4 * WW * CC + (4 * g) * CC + cc;
            unsigned u0 = f2b(q[0]);
            unsigned u1 = f2b(q[CC]);
            unsigned u2 = f2b(q[2 * CC]);
            unsigned u3 = f2b(q[3 * CC]);
            unsigned r = __byte_perm(u0, u1, 0x0040);
            r = __byte_perm(r, u2, 0x0410);
            r = __byte_perm(r, u3, 0x4210);
            R4sm[cc][g] = r;
        }
    }
    __syncthreads();

    // ---- Main loop: two float4 groups per lane (g1 = 2*lane, g2 = 2*lane+1)
    bool act1 = (lane < 28);   // g1 <= 54
    bool act2 = (lane < 27);   // g2 <= 54

    if (act1) {
        const unsigned* Vrow = &Vsm[c][0];
        uint4 va  = *(const uint4*)(Vrow + 8 * lane);      // cols 8l..8l+3
        uint4 vbm = *(const uint4*)(Vrow + 8 * lane + 4);  // cols 8l+4..8l+7
        uint4 vcc;
        unsigned ra = R4sm[c][2 * lane];
        unsigned rb = R4sm[c][2 * lane + 1];
        unsigned rc = 0;
        if (act2) {
            vcc = *(const uint4*)(Vrow + 8 * lane + 8);    // cols 8l+8..8l+11
            rc = R4sm[c][2 * lane + 2];
        }

        float* obase = out + (((size_t)(b * HO + ho) * CC + c) * FF) * WO + 8 * lane;
        const int pbase = c * FF;

#pragma unroll 2
        for (int ff = 0; ff < FF; ff++) {
            unsigned Kv0 = Wsm[0][pbase + ff];
            unsigned Kv1 = Wsm[1][pbase + ff];
            unsigned Kv2 = Wsm[2][pbase + ff];
            unsigned Kv3 = Wsm[3][pbase + ff];
            unsigned Kv4 = Wsm[4][pbase + ff];
            unsigned K4  = Wsm[5][pbase + ff];
            unsigned k44 = Wsm[6][pbase + ff];

            // Byte-shifted row-4 weight words (shared by both groups)
            unsigned lo1 = K4 << 8,  hi1 = (K4 >> 24) | (k44 << 8);
            unsigned lo2 = K4 << 16, hi2 = (K4 >> 16) | (k44 << 16);
            unsigned lo3 = K4 << 24, hi3 = (K4 >> 8)  | (k44 << 24);

            float* pb = obase + ff * WO;
            conv_group(va, vbm, ra, rb,
                       Kv0, Kv1, Kv2, Kv3, Kv4,
                       K4, lo1, lo2, lo3, k44, hi1, hi2, hi3, pb);
            if (act2)
                conv_group(vbm, vcc, rb, rc,
                           Kv0, Kv1, Kv2, Kv3, Kv4,
                           K4, lo1, lo2, lo3, k44, hi1, hi2, hi3, pb + 4);
        }
    }
}

// -------------------------------------------------------------------------
// kernel_launch: ONE launch, graph-capturable, no allocations, no scratch.
// -------------------------------------------------------------------------
extern "C" void kernel_launch(void* const* d_in, const int* in_sizes, int n_in,
                              void* d_out, int out_size) {
    const float* inputs = (const float*)d_in[0];  // [4,224,224,16] f32
    const float* kernel = (const float*)d_in[1];  // [5,5,16,32]    f32
    float* out = (float*)d_out;                   // [4,220,16,32,220] f32

    conv_fused_kernel<<<BB * HO, 512>>>(inputs, kernel, out);
}

// round 12
// speedup vs baseline: 1.1324x; 1.1324x over previous
#include <cuda_runtime.h>
#include <cstdint>

// Fixed problem shapes
#define BB 4
#define HH 224
#define WW 224
#define CC 16
#define FF 32
#define HO 220
#define WO 220
#define WG (WW / 4)   // 56 u32 words per planar row

#define MAGIC_I 0x4B400000
#define MAGIC_F 12582912.0f

// Channel-planar u8 scratch: P[b][c][h][w] (3.2 MB static device global)
__device__ unsigned char g_planar[BB * CC * HH * WW];

__device__ __forceinline__ int dp4a_us(unsigned a, unsigned b, int c) {
    int d;
    asm("dp4a.u32.s32 %0, %1, %2, %3;" : "=r"(d) : "r"(a), "r"(b), "r"(c));
    return d;
}

// -------------------------------------------------------------------------
// Prepass: NHWC fp32 -> planar u8, smem-transposed so reads AND writes coalesce.
// -------------------------------------------------------------------------
__global__ __launch_bounds__(256) void prepass_kernel(const float* __restrict__ in) {
    __shared__ unsigned char sm[CC][WW];
    int bh = blockIdx.x;
    int b = bh / HH, h = bh % HH;
    const float* row = in + (size_t)(b * HH + h) * WW * CC;

    for (int l = threadIdx.x; l < WW * CC; l += 256) {
        int w = l >> 4, c = l & 15;             // l = w*16 + c (contiguous read)
        sm[c][w] = (unsigned char)(int)row[l];
    }
    __syncthreads();

    unsigned* dst = (unsigned*)g_planar;
    for (int l = threadIdx.x; l < CC * WG; l += 256) {
        int c = l / WG, g = l % WG;
        unsigned v = (unsigned)sm[c][4 * g]
                   | ((unsigned)sm[c][4 * g + 1] << 8)
                   | ((unsigned)sm[c][4 * g + 2] << 16)
                   | ((unsigned)sm[c][4 * g + 3] << 24);
        dst[((b * CC + c) * HH + h) * WG + g] = v;
    }
}

// -------------------------------------------------------------------------
// Main conv kernel (round-8 structure + vectorized precomputed weights +
// magic-constant accumulator fold).
// grid = B*HO (880). 512 threads = 16 warps = channels; lane = wo-group.
// Weight table in smem, 13 words per (c,f):
//   W0 = (Kv0,Kv1,Kv2,Kv3)   vertical-packed kernel cols 0..3 (rows 0-3)
//   W1 = (Kv4, K4,  lo1, lo2) K4 = horiz row-4 word; lo_s = K4 << 8s
//   W2 = (lo3, k44, hi1, hi2) hi_s = (K4 >> (32-8s)) | (k44 << 8s)
//   W3 = hi3
// Per ff-iteration: 3 LDS.128 + 1 LDS.32 + 28 dp4a + 4 FADD + 1 STG.128.
// -------------------------------------------------------------------------
__global__ __launch_bounds__(512, 3) void conv_main_kernel(
    const float* __restrict__ kern, float* __restrict__ out)
{
    __shared__ __align__(16) unsigned Vsm[CC][WW];    // 14336 B
    __shared__ unsigned R4sm[CC][WG];                 // 3584 B
    __shared__ __align__(16) uint4 W0sm[CC * FF];     // 8192 B
    __shared__ __align__(16) uint4 W1sm[CC * FF];     // 8192 B
    __shared__ __align__(16) uint4 W2sm[CC * FF];     // 8192 B
    __shared__ unsigned W3sm[CC * FF];                // 2048 B   (44544 total)

    int bid = blockIdx.x;
    int ho = bid % HO;
    int b = bid / HO;
    int tid = threadIdx.x;
    int c = tid >> 5;       // warp = channel
    int lane = tid & 31;

    // ---- Pack + precompute weights: thread = (c,f) pair = tid ----
    {
        int kk[25];
#pragma unroll
        for (int t = 0; t < 25; t++)
            kk[t] = (int)kern[t * (CC * FF) + tid];   // ((i*5+j)*CC+c)*FF+f
        unsigned Kv[5];
#pragma unroll
        for (int j = 0; j < 5; j++)
            Kv[j] = ((unsigned)(kk[j] & 0xFF))
                  | ((unsigned)(kk[5 + j] & 0xFF) << 8)
                  | ((unsigned)(kk[10 + j] & 0xFF) << 16)
                  | ((unsigned)(kk[15 + j] & 0xFF) << 24);
        unsigned K4 = ((unsigned)(kk[20] & 0xFF))
                    | ((unsigned)(kk[21] & 0xFF) << 8)
                    | ((unsigned)(kk[22] & 0xFF) << 16)
                    | ((unsigned)(kk[23] & 0xFF) << 24);
        unsigned k44 = (unsigned)(kk[24] & 0xFF);

        W0sm[tid] = make_uint4(Kv[0], Kv[1], Kv[2], Kv[3]);
        W1sm[tid] = make_uint4(Kv[4], K4, K4 << 8, K4 << 16);
        W2sm[tid] = make_uint4(K4 << 24, k44,
                               (K4 >> 24) | (k44 << 8),
                               (K4 >> 16) | (k44 << 16));
        W3sm[tid] = (K4 >> 8) | (k44 << 24);
    }

    // ---- Stage 5 planar rows; build vertical words with 8-PRMT transpose ----
    const unsigned* P = (const unsigned*)g_planar;
    for (int l = tid; l < CC * WG; l += 512) {
        int cc = l / WG, g = l % WG;
        const unsigned* base = P + ((size_t)(b * CC + cc) * HH + ho) * WG + g;
        unsigned w0 = base[0 * WG];
        unsigned w1 = base[1 * WG];
        unsigned w2 = base[2 * WG];
        unsigned w3 = base[3 * WG];
        unsigned w4 = base[4 * WG];
        unsigned t0 = __byte_perm(w0, w1, 0x5140);
        unsigned t1 = __byte_perm(w0, w1, 0x7362);
        unsigned t2 = __byte_perm(w2, w3, 0x5140);
        unsigned t3 = __byte_perm(w2, w3, 0x7362);
        uint4 v;
        v.x = __byte_perm(t0, t2, 0x5410);
        v.y = __byte_perm(t0, t2, 0x7632);
        v.z = __byte_perm(t1, t3, 0x5410);
        v.w = __byte_perm(t1, t3, 0x7632);
        *(uint4*)&Vsm[cc][4 * g] = v;
        R4sm[cc][g] = w4;
    }
    __syncthreads();

    const unsigned* Vrow = &Vsm[c][0];
    const unsigned* R4 = &R4sm[c][0];
    float* rowbase = out + ((size_t)(b * HO + ho) * CC + c) * FF * WO;
    const int pbase = c * FF;

#pragma unroll
    for (int pass = 0; pass < 2; pass++) {
        int g = lane + pass * 32;
        bool act = (g < 55);                 // 55 float4 groups cover WO=220
        uint4 va, vb;
        unsigned ra, rb;
        if (act) {
            va = *(const uint4*)(Vrow + 4 * g);       // cols 4g..4g+3
            vb = *(const uint4*)(Vrow + 4 * g + 4);   // cols 4g+4..4g+7
            ra = R4[g];
            rb = R4[g + 1];
        }
        float* pb = rowbase + 4 * g;

        for (int ff = 0; ff < FF; ff++) {
            // Broadcast vector weight fetch for (c, ff): 3x LDS.128 + LDS.32
            uint4 w0 = W0sm[pbase + ff];   // Kv0..Kv3
            uint4 w1 = W1sm[pbase + ff];   // Kv4, lo0(K4), lo1, lo2
            uint4 w2 = W2sm[pbase + ff];   // lo3, hi0(k44), hi1, hi2
            unsigned hi3 = W3sm[pbase + ff];

            if (act) {
                // s = 0 : cols 4g .. 4g+4
                int a0 = dp4a_us(va.x, w0.x, MAGIC_I);
                a0 = dp4a_us(va.y, w0.y, a0);
                a0 = dp4a_us(va.z, w0.z, a0);
                a0 = dp4a_us(va.w, w0.w, a0);
                a0 = dp4a_us(vb.x, w1.x, a0);
                a0 = dp4a_us(ra, w1.y, a0);
                a0 = dp4a_us(rb, w2.y, a0);
                // s = 1
                int a1 = dp4a_us(va.y, w0.x, MAGIC_I);
                a1 = dp4a_us(va.z, w0.y, a1);
                a1 = dp4a_us(va.w, w0.z, a1);
                a1 = dp4a_us(vb.x, w0.w, a1);
                a1 = dp4a_us(vb.y, w1.x, a1);
                a1 = dp4a_us(ra, w1.z, a1);
                a1 = dp4a_us(rb, w2.z, a1);
                // s = 2
                int a2 = dp4a_us(va.z, w0.x, MAGIC_I);
                a2 = dp4a_us(va.w, w0.y, a2);
                a2 = dp4a_us(vb.x, w0.z, a2);
                a2 = dp4a_us(vb.y, w0.w, a2);
                a2 = dp4a_us(vb.z, w1.x, a2);
                a2 = dp4a_us(ra, w1.w, a2);
                a2 = dp4a_us(rb, w2.w, a2);
                // s = 3
                int a3 = dp4a_us(va.w, w0.x, MAGIC_I);
                a3 = dp4a_us(vb.x, w0.y, a3);
                a3 = dp4a_us(vb.y, w0.z, a3);
                a3 = dp4a_us(vb.z, w0.w, a3);
                a3 = dp4a_us(vb.w, w1.x, a3);
                a3 = dp4a_us(ra, w2.x, a3);
                a3 = dp4a_us(rb, hi3, a3);

                float4 o = make_float4(__int_as_float(a0) - MAGIC_F,
                                       __int_as_float(a1) - MAGIC_F,
                                       __int_as_float(a2) - MAGIC_F,
                                       __int_as_float(a3) - MAGIC_F);
                *(float4*)(pb + ff * WO) = o;   // coalesced: 512B per warp-store
            }
        }
    }
}

// -------------------------------------------------------------------------
// kernel_launch: prepass + main conv. Graph-capturable: 2 launches, no sync,
// no allocation (scratch is a static __device__ array).
// -------------------------------------------------------------------------
extern "C" void kernel_launch(void* const* d_in, const int* in_sizes, int n_in,
                              void* d_out, int out_size) {
    const float* inputs = (const float*)d_in[0];  // [4,224,224,16] f32
    const float* kernel = (const float*)d_in[1];  // [5,5,16,32]    f32
    float* out = (float*)d_out;                   // [4,220,16,32,220] f32

    prepass_kernel<<<BB * HH, 256>>>(inputs);
    conv_main_kernel<<<BB * HO, 512>>>(kernel, out);
}

// round 13
// speedup vs baseline: 1.2245x; 1.0813x over previous
#include <cuda_runtime.h>
#include <cstdint>

// Fixed problem shapes
#define BB 4
#define HH 224
#define WW 224
#define CC 16
#define FF 32
#define HO 220
#define WO 220
#define WG (WW / 4)   // 56 u32 words per planar row

#define MAGIC_I 0x4B400000
#define MAGIC_F 12582912.0f

// Channel-planar u8 scratch: P[b][c][h][w] (3.2 MB static device global)
__device__ unsigned char g_planar[BB * CC * HH * WW];

__device__ __forceinline__ int dp4a_us(unsigned a, unsigned b, int c) {
    int d;
    asm("dp4a.u32.s32 %0, %1, %2, %3;" : "=r"(d) : "r"(a), "r"(b), "r"(c));
    return d;
}

// -------------------------------------------------------------------------
// Prepass: NHWC fp32 -> planar u8, smem-transposed so reads AND writes coalesce.
// -------------------------------------------------------------------------
__global__ __launch_bounds__(256) void prepass_kernel(const float* __restrict__ in) {
    __shared__ unsigned char sm[CC][WW];
    int bh = blockIdx.x;
    int b = bh / HH, h = bh % HH;
    const float* row = in + (size_t)(b * HH + h) * WW * CC;

    for (int l = threadIdx.x; l < WW * CC; l += 256) {
        int w = l >> 4, c = l & 15;             // l = w*16 + c (contiguous read)
        sm[c][w] = (unsigned char)(int)row[l];
    }
    __syncthreads();

    unsigned* dst = (unsigned*)g_planar;
    for (int l = threadIdx.x; l < CC * WG; l += 256) {
        int c = l / WG, g = l % WG;
        unsigned v = (unsigned)sm[c][4 * g]
                   | ((unsigned)sm[c][4 * g + 1] << 8)
                   | ((unsigned)sm[c][4 * g + 2] << 16)
                   | ((unsigned)sm[c][4 * g + 3] << 24);
        dst[((b * CC + c) * HH + h) * WG + g] = v;
    }
}

// Compute one float4 output group from vertical words A,B (+row-4 ra/rb) and
// the 13 precomputed weight words; write with streaming hint.
__device__ __forceinline__ void conv_group4(
    uint4 va, uint4 vb, unsigned ra, unsigned rb,
    uint4 w0, uint4 w1, uint4 w2, unsigned hi3, float* pb)
{
    // s = 0 : cols 4g .. 4g+4
    int a0 = dp4a_us(va.x, w0.x, MAGIC_I);
    a0 = dp4a_us(va.y, w0.y, a0);
    a0 = dp4a_us(va.z, w0.z, a0);
    a0 = dp4a_us(va.w, w0.w, a0);
    a0 = dp4a_us(vb.x, w1.x, a0);
    a0 = dp4a_us(ra, w1.y, a0);
    a0 = dp4a_us(rb, w2.y, a0);
    // s = 1
    int a1 = dp4a_us(va.y, w0.x, MAGIC_I);
    a1 = dp4a_us(va.z, w0.y, a1);
    a1 = dp4a_us(va.w, w0.z, a1);
    a1 = dp4a_us(vb.x, w0.w, a1);
    a1 = dp4a_us(vb.y, w1.x, a1);
    a1 = dp4a_us(ra, w1.z, a1);
    a1 = dp4a_us(rb, w2.z, a1);
    // s = 2
    int a2 = dp4a_us(va.z, w0.x, MAGIC_I);
    a2 = dp4a_us(va.w, w0.y, a2);
    a2 = dp4a_us(vb.x, w0.z, a2);
    a2 = dp4a_us(vb.y, w0.w, a2);
    a2 = dp4a_us(vb.z, w1.x, a2);
    a2 = dp4a_us(ra, w1.w, a2);
    a2 = dp4a_us(rb, w2.w, a2);
    // s = 3
    int a3 = dp4a_us(va.w, w0.x, MAGIC_I);
    a3 = dp4a_us(vb.x, w0.y, a3);
    a3 = dp4a_us(vb.y, w0.z, a3);
    a3 = dp4a_us(vb.z, w0.w, a3);
    a3 = dp4a_us(vb.w, w1.x, a3);
    a3 = dp4a_us(ra, w2.x, a3);
    a3 = dp4a_us(rb, hi3, a3);

    float4 o = make_float4(__int_as_float(a0) - MAGIC_F,
                           __int_as_float(a1) - MAGIC_F,
                           __int_as_float(a2) - MAGIC_F,
                           __int_as_float(a3) - MAGIC_F);
    __stcs((float4*)pb, o);   // streaming: write-once output, evict-first
}

// -------------------------------------------------------------------------
// Main conv kernel.
// grid = B*HO*2 (1760). block = 256 threads = 8 warps = 8 channels
// (chalf picks channels 0-7 or 8-15). lane = wo-group; 2 passes cover 55
// groups. ff loop advances by 2 with both iterations' weights loaded up
// front (software pipeline: >=56 independent dp4a between LDS and use).
// Weight table in smem, 13 words per (c,f):
//   W0 = (Kv0,Kv1,Kv2,Kv3)   vertical-packed kernel cols 0..3 (rows 0-3)
//   W1 = (Kv4, K4,  lo1, lo2), W2 = (lo3, k44, hi1, hi2), W3 = hi3
// -------------------------------------------------------------------------
__global__ __launch_bounds__(256, 6) void conv_main_kernel(
    const float* __restrict__ kern, float* __restrict__ out)
{
    __shared__ __align__(16) unsigned Vsm[8][WW];    // 7168 B
    __shared__ unsigned R4sm[8][WG];                 // 1792 B
    __shared__ __align__(16) uint4 W0sm[256];        // 4096 B
    __shared__ __align__(16) uint4 W1sm[256];        // 4096 B
    __shared__ __align__(16) uint4 W2sm[256];        // 4096 B
    __shared__ unsigned W3sm[256];                   // 1024 B  (22272 total)

    int bid = blockIdx.x;
    int chalf = bid & 1;
    int t = bid >> 1;
    int ho = t % HO;
    int b = t / HO;
    int tid = threadIdx.x;
    int wid = tid >> 5;              // local channel 0..7
    int lane = tid & 31;
    int cg = chalf * 8 + wid;        // global channel

    // ---- Pack + precompute weights: thread = (local c, f) = (wid, lane) ----
    {
        int kk[25];
#pragma unroll
        for (int tt = 0; tt < 25; tt++)
            kk[tt] = (int)kern[tt * (CC * FF) + cg * FF + lane];
        unsigned Kv[5];
#pragma unroll
        for (int j = 0; j < 5; j++)
            Kv[j] = ((unsigned)(kk[j] & 0xFF))
                  | ((unsigned)(kk[5 + j] & 0xFF) << 8)
                  | ((unsigned)(kk[10 + j] & 0xFF) << 16)
                  | ((unsigned)(kk[15 + j] & 0xFF) << 24);
        unsigned K4 = ((unsigned)(kk[20] & 0xFF))
                    | ((unsigned)(kk[21] & 0xFF) << 8)
                    | ((unsigned)(kk[22] & 0xFF) << 16)
                    | ((unsigned)(kk[23] & 0xFF) << 24);
        unsigned k44 = (unsigned)(kk[24] & 0xFF);

        W0sm[tid] = make_uint4(Kv[0], Kv[1], Kv[2], Kv[3]);
        W1sm[tid] = make_uint4(Kv[4], K4, K4 << 8, K4 << 16);
        W2sm[tid] = make_uint4(K4 << 24, k44,
                               (K4 >> 24) | (k44 << 8),
                               (K4 >> 16) | (k44 << 16));
        W3sm[tid] = (K4 >> 8) | (k44 << 24);
    }

    // ---- Stage 5 planar rows for our 8 channels; 8-PRMT vertical transpose ----
    const unsigned* P = (const unsigned*)g_planar;
    for (int l = tid; l < 8 * WG; l += 256) {
        int cc = l / WG, g = l % WG;
        const unsigned* base =
            P + ((size_t)(b * CC + chalf * 8 + cc) * HH + ho) * WG + g;
        unsigned r0 = base[0 * WG];
        unsigned r1 = base[1 * WG];
        unsigned r2 = base[2 * WG];
        unsigned r3 = base[3 * WG];
        unsigned r4 = base[4 * WG];
        unsigned t0 = __byte_perm(r0, r1, 0x5140);
        unsigned t1 = __byte_perm(r0, r1, 0x7362);
        unsigned t2 = __byte_perm(r2, r3, 0x5140);
        unsigned t3 = __byte_perm(r2, r3, 0x7362);
        uint4 v;
        v.x = __byte_perm(t0, t2, 0x5410);
        v.y = __byte_perm(t0, t2, 0x7632);
        v.z = __byte_perm(t1, t3, 0x5410);
        v.w = __byte_perm(t1, t3, 0x7632);
        *(uint4*)&Vsm[cc][4 * g] = v;
        R4sm[cc][g] = r4;
    }
    __syncthreads();

    const unsigned* Vrow = &Vsm[wid][0];
    const unsigned* R4 = &R4sm[wid][0];
    float* rowbase = out + ((size_t)(b * HO + ho) * CC + cg) * FF * WO;
    const int pbase = wid * 32;

#pragma unroll 1
    for (int pass = 0; pass < 2; pass++) {
        int g = lane + pass * 32;
        bool act = (g < 55);                 // 55 float4 groups cover WO=220
        uint4 va, vb;
        unsigned ra, rb;
        if (act) {
            va = *(const uint4*)(Vrow + 4 * g);       // cols 4g..4g+3
            vb = *(const uint4*)(Vrow + 4 * g + 4);   // cols 4g+4..4g+7
            ra = R4[g];
            rb = R4[g + 1];
        }
        float* pb = rowbase + 4 * g;

#pragma unroll 2
        for (int ff = 0; ff < FF; ff += 2) {
            // Load BOTH iterations' weights first (broadcast LDS), then run
            // 8 independent dp4a chains -> LDS latency fully covered.
            uint4 w0a = W0sm[pbase + ff];
            uint4 w1a = W1sm[pbase + ff];
            uint4 w2a = W2sm[pbase + ff];
            unsigned hi3a = W3sm[pbase + ff];
            uint4 w0b = W0sm[pbase + ff + 1];
            uint4 w1b = W1sm[pbase + ff + 1];
            uint4 w2b = W2sm[pbase + ff + 1];
            unsigned hi3b = W3sm[pbase + ff + 1];

            if (act) {
                conv_group4(va, vb, ra, rb, w0a, w1a, w2a, hi3a, pb + ff * WO);
                conv_group4(va, vb, ra, rb, w0b, w1b, w2b, hi3b, pb + (ff + 1) * WO);
            }
        }
    }
}

// -------------------------------------------------------------------------
// kernel_launch: prepass + main conv. Graph-capturable: 2 launches, no sync,
// no allocation (scratch is a static __device__ array).
// -------------------------------------------------------------------------
extern "C" void kernel_launch(void* const* d_in, const int* in_sizes, int n_in,
                              void* d_out, int out_size) {
    const float* inputs = (const float*)d_in[0];  // [4,224,224,16] f32
    const float* kernel = (const float*)d_in[1];  // [5,5,16,32]    f32
    float* out = (float*)d_out;                   // [4,220,16,32,220] f32

    prepass_kernel<<<BB * HH, 256>>>(inputs);
    conv_main_kernel<<<BB * HO * 2, 256>>>(kernel, out);
}

// round 14
// speedup vs baseline: 1.3476x; 1.1005x over previous
#include <cuda_runtime.h>
#include <cstdint>

// Fixed problem shapes
#define BB 4
#define HH 224
#define WW 224
#define CC 16
#define FF 32
#define HO 220
#define WO 220
#define WG (WW / 4)   // 56 u32 words per planar row

#define MAGIC_I 0x4B400000
#define MAGIC_F 12582912.0f

// Channel-planar u8 scratch: P[b][c][h][w] (3.2 MB static device global)
__device__ unsigned char g_planar[BB * CC * HH * WW];

__device__ __forceinline__ int dp4a_us(unsigned a, unsigned b, int c) {
    int d;
    asm("dp4a.u32.s32 %0, %1, %2, %3;" : "=r"(d) : "r"(a), "r"(b), "r"(c));
    return d;
}

// Unpack byte t (0..3) of word into an exact float in [0,255]:
// PRMT builds 0x4B4000bb, FSUB removes the magic offset. 1 alu + 1 fma op.
__device__ __forceinline__ float byte2f(unsigned word, int t) {
    unsigned r = __byte_perm(word, 0x4B400000u, 0x7650u + (unsigned)t);
    return __uint_as_float(r) - MAGIC_F;
}

// -------------------------------------------------------------------------
// Prepass: NHWC fp32 -> planar u8, smem-transposed so reads AND writes coalesce.
// -------------------------------------------------------------------------
__global__ __launch_bounds__(256) void prepass_kernel(const float* __restrict__ in) {
    __shared__ unsigned char sm[CC][WW + 4];   // +4: conflict-free column writes
    int bh = blockIdx.x;
    int b = bh / HH, h = bh % HH;
    const float* row = in + (size_t)(b * HH + h) * WW * CC;

    for (int l = threadIdx.x; l < WW * CC; l += 256) {
        int w = l >> 4, c = l & 15;             // l = w*16 + c (contiguous read)
        sm[c][w] = (unsigned char)(int)row[l];
    }
    __syncthreads();

    unsigned* dst = (unsigned*)g_planar;
    for (int l = threadIdx.x; l < CC * WG; l += 256) {
        int c = l / WG, g = l % WG;
        unsigned v = (unsigned)sm[c][4 * g]
                   | ((unsigned)sm[c][4 * g + 1] << 8)
                   | ((unsigned)sm[c][4 * g + 2] << 16)
                   | ((unsigned)sm[c][4 * g + 3] << 24);
        dst[((b * CC + c) * HH + h) * WG + g] = v;
    }
}

// One float4 output group: rows 0-3 via 5 vertical dp4a per output (IDP pipe),
// row 4 via 5 FFMA per output on pre-unpacked floats (FMA pipe).
__device__ __forceinline__ void conv_group4(
    uint4 va, uint4 vb, const float* X4,
    uint4 w0, unsigned kv4, float4 wa, float wb, float* pb)
{
    // dp4a part: rows ho..ho+3
    int a0 = dp4a_us(va.x, w0.x, MAGIC_I);
    a0 = dp4a_us(va.y, w0.y, a0);
    a0 = dp4a_us(va.z, w0.z, a0);
    a0 = dp4a_us(va.w, w0.w, a0);
    a0 = dp4a_us(vb.x, kv4, a0);

    int a1 = dp4a_us(va.y, w0.x, MAGIC_I);
    a1 = dp4a_us(va.z, w0.y, a1);
    a1 = dp4a_us(va.w, w0.z, a1);
    a1 = dp4a_us(vb.x, w0.w, a1);
    a1 = dp4a_us(vb.y, kv4, a1);

    int a2 = dp4a_us(va.z, w0.x, MAGIC_I);
    a2 = dp4a_us(va.w, w0.y, a2);
    a2 = dp4a_us(vb.x, w0.z, a2);
    a2 = dp4a_us(vb.y, w0.w, a2);
    a2 = dp4a_us(vb.z, kv4, a2);

    int a3 = dp4a_us(va.w, w0.x, MAGIC_I);
    a3 = dp4a_us(vb.x, w0.y, a3);
    a3 = dp4a_us(vb.y, w0.z, a3);
    a3 = dp4a_us(vb.z, w0.w, a3);
    a3 = dp4a_us(vb.w, kv4, a3);

    // FFMA part: row ho+4, taps wa.x..wa.w, wb over X4[s..s+4].
    // as_float(MAGIC_I + v) = 12582912 + v (exact, |v| < 2^22); chain FFMAs
    // on top (all intermediates exact integers < 2^24), subtract magic last.
    float f0 = __int_as_float(a0);
    float f1 = __int_as_float(a1);
    float f2 = __int_as_float(a2);
    float f3 = __int_as_float(a3);

    f0 = fmaf(X4[0], wa.x, f0);
    f1 = fmaf(X4[1], wa.x, f1);
    f2 = fmaf(X4[2], wa.x, f2);
    f3 = fmaf(X4[3], wa.x, f3);
    f0 = fmaf(X4[1], wa.y, f0);
    f1 = fmaf(X4[2], wa.y, f1);
    f2 = fmaf(X4[3], wa.y, f2);
    f3 = fmaf(X4[4], wa.y, f3);
    f0 = fmaf(X4[2], wa.z, f0);
    f1 = fmaf(X4[3], wa.z, f1);
    f2 = fmaf(X4[4], wa.z, f2);
    f3 = fmaf(X4[5], wa.z, f3);
    f0 = fmaf(X4[3], wa.w, f0);
    f1 = fmaf(X4[4], wa.w, f1);
    f2 = fmaf(X4[5], wa.w, f2);
    f3 = fmaf(X4[6], wa.w, f3);
    f0 = fmaf(X4[4], wb, f0);
    f1 = fmaf(X4[5], wb, f1);
    f2 = fmaf(X4[6], wb, f2);
    f3 = fmaf(X4[7], wb, f3);

    float4 o = make_float4(f0 - MAGIC_F, f1 - MAGIC_F,
                           f2 - MAGIC_F, f3 - MAGIC_F);
    __stcs((float4*)pb, o);   // streaming: write-once output
}

// -------------------------------------------------------------------------
// Main conv kernel.
// grid = B*HO*2 (1760). block = 256 threads = 8 warps = 8 channels
// (chalf picks channels 0-7 or 8-15). lane = wo-group; 2 passes cover 55
// groups. ff advances by 2 with both weight sets loaded up front.
// Weight tables per (c,f): W0 = (Kv0..Kv3) vertical rows0-3 packed,
// Wk4 = Kv4, W4a/W4b = row-4 weights as fp32.
// -------------------------------------------------------------------------
__global__ __launch_bounds__(256, 5) void conv_main_kernel(
    const float* __restrict__ kern, float* __restrict__ out)
{
    __shared__ __align__(16) unsigned Vsm[8][WW];    // 7168 B
    __shared__ unsigned R4sm[8][WG];                 // 1792 B
    __shared__ __align__(16) uint4 W0sm[256];        // 4096 B
    __shared__ unsigned Wk4sm[256];                  // 1024 B
    __shared__ __align__(16) float4 W4asm[256];      // 4096 B
    __shared__ float W4bsm[256];                     // 1024 B  (19200 total)

    int bid = blockIdx.x;
    int chalf = bid & 1;
    int t = bid >> 1;
    int ho = t % HO;
    int b = t / HO;
    int tid = threadIdx.x;
    int wid = tid >> 5;              // local channel 0..7
    int lane = tid & 31;
    int cg = chalf * 8 + wid;        // global channel

    // ---- Pack weights: thread = (local c, f) = (wid, lane) ----
    {
        int kk[25];
#pragma unroll
        for (int tt = 0; tt < 25; tt++)
            kk[tt] = (int)kern[tt * (CC * FF) + cg * FF + lane];
        unsigned Kv[5];
#pragma unroll
        for (int j = 0; j < 5; j++)
            Kv[j] = ((unsigned)(kk[j] & 0xFF))
                  | ((unsigned)(kk[5 + j] & 0xFF) << 8)
                  | ((unsigned)(kk[10 + j] & 0xFF) << 16)
                  | ((unsigned)(kk[15 + j] & 0xFF) << 24);
        W0sm[tid] = make_uint4(Kv[0], Kv[1], Kv[2], Kv[3]);
        Wk4sm[tid] = Kv[4];
        W4asm[tid] = make_float4((float)kk[20], (float)kk[21],
                                 (float)kk[22], (float)kk[23]);
        W4bsm[tid] = (float)kk[24];
    }

    // ---- Stage 5 planar rows for our 8 channels; 8-PRMT vertical transpose ----
    const unsigned* P = (const unsigned*)g_planar;
    for (int l = tid; l < 8 * WG; l += 256) {
        int cc = l / WG, g = l % WG;
        const unsigned* base =
            P + ((size_t)(b * CC + chalf * 8 + cc) * HH + ho) * WG + g;
        unsigned r0 = base[0 * WG];
        unsigned r1 = base[1 * WG];
        unsigned r2 = base[2 * WG];
        unsigned r3 = base[3 * WG];
        unsigned r4 = base[4 * WG];
        unsigned t0 = __byte_perm(r0, r1, 0x5140);
        unsigned t1 = __byte_perm(r0, r1, 0x7362);
        unsigned t2 = __byte_perm(r2, r3, 0x5140);
        unsigned t3 = __byte_perm(r2, r3, 0x7362);
        uint4 v;
        v.x = __byte_perm(t0, t2, 0x5410);
        v.y = __byte_perm(t0, t2, 0x7632);
        v.z = __byte_perm(t1, t3, 0x5410);
        v.w = __byte_perm(t1, t3, 0x7632);
        *(uint4*)&Vsm[cc][4 * g] = v;
        R4sm[cc][g] = r4;
    }
    __syncthreads();

    const unsigned* Vrow = &Vsm[wid][0];
    const unsigned* R4 = &R4sm[wid][0];
    float* rowbase = out + ((size_t)(b * HO + ho) * CC + cg) * FF * WO;
    const int pbase = wid * 32;

#pragma unroll 1
    for (int pass = 0; pass < 2; pass++) {
        int g = lane + pass * 32;
        bool act = (g < 55);                 // 55 float4 groups cover WO=220
        uint4 va, vb;
        float X4[8];                         // unpacked row ho+4, cols 4g..4g+7
        if (act) {
            va = *(const uint4*)(Vrow + 4 * g);       // cols 4g..4g+3
            vb = *(const uint4*)(Vrow + 4 * g + 4);   // cols 4g+4..4g+7
            unsigned ra = R4[g];
            unsigned rb = R4[g + 1];
#pragma unroll
            for (int s = 0; s < 4; s++) {
                X4[s] = byte2f(ra, s);
                X4[4 + s] = byte2f(rb, s);
            }
        }
        float* pb = rowbase + 4 * g;

#pragma unroll 2
        for (int ff = 0; ff < FF; ff += 2) {
            // Load BOTH iterations' weights first (broadcast LDS), then run
            // independent dp4a/FFMA chains -> LDS latency fully covered.
            uint4 w0a = W0sm[pbase + ff];
            unsigned kv4a = Wk4sm[pbase + ff];
            float4 waa = W4asm[pbase + ff];
            float wba = W4bsm[pbase + ff];
            uint4 w0b = W0sm[pbase + ff + 1];
            unsigned kv4b = Wk4sm[pbase + ff + 1];
            float4 wab = W4asm[pbase + ff + 1];
            float wbb = W4bsm[pbase + ff + 1];

            if (act) {
                conv_group4(va, vb, X4, w0a, kv4a, waa, wba, pb + ff * WO);
                conv_group4(va, vb, X4, w0b, kv4b, wab, wbb, pb + (ff + 1) * WO);
            }
        }
    }
}

// -------------------------------------------------------------------------
// kernel_launch: prepass + main conv. Graph-capturable: 2 launches, no sync,
// no allocation (scratch is a static __device__ array).
// -------------------------------------------------------------------------
extern "C" void kernel_launch(void* const* d_in, const int* in_sizes, int n_in,
                              void* d_out, int out_size) {
    const float* inputs = (const float*)d_in[0];  // [4,224,224,16] f32
    const float* kernel = (const float*)d_in[1];  // [5,5,16,32]    f32
    float* out = (float*)d_out;                   // [4,220,16,32,220] f32

    prepass_kernel<<<BB * HH, 256>>>(inputs);
    conv_main_kernel<<<BB * HO * 2, 256>>>(kernel, out);
}

// round 15
// speedup vs baseline: 1.4789x; 1.0974x over previous
#include <cuda_runtime.h>
#include <cstdint>

// Fixed problem shapes
#define BB 4
#define HH 224
#define WW 224
#define CC 16
#define FF 32
#define HO 220
#define WO 220
#define WG (WW / 4)   // 56 u32 words per planar row

#define MAGIC_I 0x4B400000
#define MAGIC_F 12582912.0f
#define NMAGIC2 0xCB400000CB400000ULL   // f32x2 pair (-12582912, -12582912)

typedef unsigned long long u64;

// Channel-planar u8 scratch: P[b][c][h][w] (3.2 MB static device global)
__device__ unsigned char g_planar[BB * CC * HH * WW];

__device__ __forceinline__ int dp4a_us(unsigned a, unsigned b, int c) {
    int d;
    asm("dp4a.u32.s32 %0, %1, %2, %3;" : "=r"(d) : "r"(a), "r"(b), "r"(c));
    return d;
}

// f32x2 packed ops (sm_103a; FFMA2 reachable only via PTX)
__device__ __forceinline__ u64 pack2(float lo, float hi) {
    u64 r;
    asm("mov.b64 %0, {%1, %2};" : "=l"(r) : "f"(lo), "f"(hi));
    return r;
}
__device__ __forceinline__ u64 fma2(u64 a, u64 b, u64 c) {
    u64 d;
    asm("fma.rn.f32x2 %0, %1, %2, %3;" : "=l"(d) : "l"(a), "l"(b), "l"(c));
    return d;
}
__device__ __forceinline__ u64 add2(u64 a, u64 b) {
    u64 d;
    asm("add.rn.f32x2 %0, %1, %2;" : "=l"(d) : "l"(a), "l"(b));
    return d;
}

// Magic-offset word for an integer-valued float in [0,255]: low byte == value.
__device__ __forceinline__ unsigned f2b(float f) {
    return __float_as_uint(f + 8388608.0f);
}
// Unpack byte t (0..3) of word into an exact float (PRMT + FSUB).
__device__ __forceinline__ float byte2f(unsigned word, int t) {
    unsigned r = __byte_perm(word, 0x4B400000u, 0x7650u + (unsigned)t);
    return __uint_as_float(r) - MAGIC_F;
}

// -------------------------------------------------------------------------
// Prepass: NHWC fp32 -> planar u8. 2 image rows per block (halved fixed
// costs), FADD-magic conversion (no F2I), aligned u32 phase-2 reads.
// -------------------------------------------------------------------------
__global__ __launch_bounds__(512) void prepass_kernel(const float* __restrict__ in) {
    __shared__ unsigned char sm[2][CC][WW + 4];
    int bh2 = blockIdx.x;                 // 0 .. BB*HH/2-1
    int b = bh2 / (HH / 2), hr = bh2 % (HH / 2);
    int h0 = hr * 2;
    const float* row = in + (size_t)(b * HH + h0) * WW * CC;

    for (int l = threadIdx.x; l < 2 * WW * CC; l += 512) {
        int r = l / (WW * CC), k = l % (WW * CC);
        int w = k >> 4, c = k & 15;       // contiguous float reads
        sm[r][c][w] = (unsigned char)f2b(row[l]);
    }
    __syncthreads();

    unsigned* dst = (unsigned*)g_planar;
    for (int l = threadIdx.x; l < 2 * CC * WG; l += 512) {
        int r = l / (CC * WG), k = l % (CC * WG);
        int c = k / WG, g = k % WG;
        unsigned v = *(const unsigned*)&sm[r][c][4 * g];   // aligned: 228c+4g
        dst[((b * CC + c) * HH + h0 + r) * WG + g] = v;
    }
}

// One float4 output group: rows 0-3 via 20 dp4a (IDP pipe), row 4 via 10
// packed FFMA2 on pre-paired floats (FMA pipe, 2 MACs/slot).
__device__ __forceinline__ void conv_group4(
    uint4 va, uint4 vb, const u64* Xp,
    uint4 w0, unsigned kv4,
    u64 wp0, u64 wp1, u64 wp2, u64 wp3, u64 wp4, float* pb)
{
    // dp4a part: rows ho..ho+3 (accumulator starts at the i2f magic word)
    int a0 = dp4a_us(va.x, w0.x, MAGIC_I);
    a0 = dp4a_us(va.y, w0.y, a0);
    a0 = dp4a_us(va.z, w0.z, a0);
    a0 = dp4a_us(va.w, w0.w, a0);
    a0 = dp4a_us(vb.x, kv4, a0);

    int a1 = dp4a_us(va.y, w0.x, MAGIC_I);
    a1 = dp4a_us(va.z, w0.y, a1);
    a1 = dp4a_us(va.w, w0.z, a1);
    a1 = dp4a_us(vb.x, w0.w, a1);
    a1 = dp4a_us(vb.y, kv4, a1);

    int a2 = dp4a_us(va.z, w0.x, MAGIC_I);
    a2 = dp4a_us(va.w, w0.y, a2);
    a2 = dp4a_us(vb.x, w0.z, a2);
    a2 = dp4a_us(vb.y, w0.w, a2);
    a2 = dp4a_us(vb.z, kv4, a2);

    int a3 = dp4a_us(va.w, w0.x, MAGIC_I);
    a3 = dp4a_us(vb.x, w0.y, a3);
    a3 = dp4a_us(vb.y, w0.z, a3);
    a3 = dp4a_us(vb.z, w0.w, a3);
    a3 = dp4a_us(vb.w, kv4, a3);

    // f32x2 part: row ho+4. Pair (f0,f1) uses Xp[j], pair (f2,f3) Xp[j+2].
    // All intermediates exact integers offset by 12582912 (< 2^24).
    u64 f01 = pack2(__int_as_float(a0), __int_as_float(a1));
    u64 f23 = pack2(__int_as_float(a2), __int_as_float(a3));

    f01 = fma2(Xp[0], wp0, f01);
    f23 = fma2(Xp[2], wp0, f23);
    f01 = fma2(Xp[1], wp1, f01);
    f23 = fma2(Xp[3], wp1, f23);
    f01 = fma2(Xp[2], wp2, f01);
    f23 = fma2(Xp[4], wp2, f23);
    f01 = fma2(Xp[3], wp3, f01);
    f23 = fma2(Xp[5], wp3, f23);
    f01 = fma2(Xp[4], wp4, f01);
    f23 = fma2(Xp[6], wp4, f23);

    f01 = add2(f01, NMAGIC2);
    f23 = add2(f23, NMAGIC2);

    __stcs((double2*)pb, make_double2(__longlong_as_double((long long)f01),
                                      __longlong_as_double((long long)f23)));
}

// -------------------------------------------------------------------------
// Main conv kernel.
// grid = B*HO*2 (1760). block = 256 threads = 8 warps = 8 channels.
// lane = wo-group; 2 passes cover 55 groups. ff advances by 2 with both
// weight sets loaded up front (LDS latency hidden behind 66 math ops).
// Weight tables per (c,f): W0 = packed rows0-3 cols0-3, Wk4 = col4,
// WDab/WDcd/WDe = row-4 weights pre-DUPLICATED as f32x2 pairs (loads land
// directly in 64-bit regs; zero per-ff packing).
// -------------------------------------------------------------------------
__global__ __launch_bounds__(256, 4) void conv_main_kernel(
    const float* __restrict__ kern, float* __restrict__ out)
{
    __shared__ __align__(16) unsigned Vsm[8][WW];     // 7168 B
    __shared__ unsigned R4sm[8][WG];                  // 1792 B
    __shared__ __align__(16) uint4 W0sm[256];         // 4096 B
    __shared__ unsigned Wk4sm[256];                   // 1024 B
    __shared__ __align__(16) ulonglong2 WDab[256];    // 4096 B (wp0, wp1)
    __shared__ __align__(16) ulonglong2 WDcd[256];    // 4096 B (wp2, wp3)
    __shared__ u64 WDe[256];                          // 2048 B (wp4)  24320 total

    int bid = blockIdx.x;
    int chalf = bid & 1;
    int t = bid >> 1;
    int ho = t % HO;
    int b = t / HO;
    int tid = threadIdx.x;
    int wid = tid >> 5;              // local channel 0..7
    int lane = tid & 31;
    int cg = chalf * 8 + wid;        // global channel

    // ---- Pack weights: thread = (local c, f) = (wid, lane) ----
    {
        int kk[25];
#pragma unroll
        for (int tt = 0; tt < 25; tt++)
            kk[tt] = (int)kern[tt * (CC * FF) + cg * FF + lane];
        unsigned Kv[5];
#pragma unroll
        for (int j = 0; j < 5; j++)
            Kv[j] = ((unsigned)(kk[j] & 0xFF))
                  | ((unsigned)(kk[5 + j] & 0xFF) << 8)
                  | ((unsigned)(kk[10 + j] & 0xFF) << 16)
                  | ((unsigned)(kk[15 + j] & 0xFF) << 24);
        W0sm[tid] = make_uint4(Kv[0], Kv[1], Kv[2], Kv[3]);
        Wk4sm[tid] = Kv[4];
        unsigned d0 = __float_as_uint((float)kk[20]);
        unsigned d1 = __float_as_uint((float)kk[21]);
        unsigned d2 = __float_as_uint((float)kk[22]);
        unsigned d3 = __float_as_uint((float)kk[23]);
        unsigned d4 = __float_as_uint((float)kk[24]);
        WDab[tid] = make_ulonglong2(d0 | ((u64)d0 << 32), d1 | ((u64)d1 << 32));
        WDcd[tid] = make_ulonglong2(d2 | ((u64)d2 << 32), d3 | ((u64)d3 << 32));
        WDe[tid]  = d4 | ((u64)d4 << 32);
    }

    // ---- Stage 5 planar rows for our 8 channels; 8-PRMT vertical transpose ----
    const unsigned* P = (const unsigned*)g_planar;
    for (int l = tid; l < 8 * WG; l += 256) {
        int cc = l / WG, g = l % WG;
        const unsigned* base =
            P + ((size_t)(b * CC + chalf * 8 + cc) * HH + ho) * WG + g;
        unsigned r0 = base[0 * WG];
        unsigned r1 = base[1 * WG];
        unsigned r2 = base[2 * WG];
        unsigned r3 = base[3 * WG];
        unsigned r4 = base[4 * WG];
        unsigned t0 = __byte_perm(r0, r1, 0x5140);
        unsigned t1 = __byte_perm(r0, r1, 0x7362);
        unsigned t2 = __byte_perm(r2, r3, 0x5140);
        unsigned t3 = __byte_perm(r2, r3, 0x7362);
        uint4 v;
        v.x = __byte_perm(t0, t2, 0x5410);
        v.y = __byte_perm(t0, t2, 0x7632);
        v.z = __byte_perm(t1, t3, 0x5410);
        v.w = __byte_perm(t1, t3, 0x7632);
        *(uint4*)&Vsm[cc][4 * g] = v;
        R4sm[cc][g] = r4;
    }
    __syncthreads();

    const unsigned* Vrow = &Vsm[wid][0];
    const unsigned* R4 = &R4sm[wid][0];
    float* rowbase = out + ((size_t)(b * HO + ho) * CC + cg) * FF * WO;
    const int pbase = wid * 32;

#pragma unroll 1
    for (int pass = 0; pass < 2; pass++) {
        int g = lane + pass * 32;
        bool act = (g < 55);                 // 55 float4 groups cover WO=220
        uint4 va, vb;
        u64 Xp[7];                           // row ho+4 float pairs (X[j],X[j+1])
        if (act) {
            va = *(const uint4*)(Vrow + 4 * g);       // cols 4g..4g+3
            vb = *(const uint4*)(Vrow + 4 * g + 4);   // cols 4g+4..4g+7
            unsigned ra = R4[g];
            unsigned rb = R4[g + 1];
            float X4[8];
#pragma unroll
            for (int s = 0; s < 4; s++) {
                X4[s] = byte2f(ra, s);
                X4[4 + s] = byte2f(rb, s);
            }
#pragma unroll
            for (int j = 0; j < 7; j++)
                Xp[j] = pack2(X4[j], X4[j + 1]);
        }
        float* pb = rowbase + 4 * g;

#pragma unroll 2
        for (int ff = 0; ff < FF; ff += 2) {
            // Load BOTH iterations' weights first (broadcast LDS), then run
            // independent dp4a/FFMA2 chains -> LDS latency fully covered.
            uint4 w0a = W0sm[pbase + ff];
            unsigned kv4a = Wk4sm[pbase + ff];
            ulonglong2 dab_a = WDab[pbase + ff];
            ulonglong2 dcd_a = WDcd[pbase + ff];
            u64 de_a = WDe[pbase + ff];
            uint4 w0b = W0sm[pbase + ff + 1];
            unsigned kv4b = Wk4sm[pbase + ff + 1];
            ulonglong2 dab_b = WDab[pbase + ff + 1];
            ulonglong2 dcd_b = WDcd[pbase + ff + 1];
            u64 de_b = WDe[pbase + ff + 1];

            if (act) {
                conv_group4(va, vb, Xp, w0a, kv4a,
                            dab_a.x, dab_a.y, dcd_a.x, dcd_a.y, de_a,
                            pb + ff * WO);
                conv_group4(va, vb, Xp, w0b, kv4b,
                            dab_b.x, dab_b.y, dcd_b.x, dcd_b.y, de_b,
                            pb + (ff + 1) * WO);
            }
        }
    }
}

// -------------------------------------------------------------------------
// kernel_launch: prepass + main conv. Graph-capturable: 2 launches, no sync,
// no allocation (scratch is a static __device__ array).
// -------------------------------------------------------------------------
extern "C" void kernel_launch(void* const* d_in, const int* in_sizes, int n_in,
                              void* d_out, int out_size) {
    const float* inputs = (const float*)d_in[0];  // [4,224,224,16] f32
    const float* kernel = (const float*)d_in[1];  // [5,5,16,32]    f32
    float* out = (float*)d_out;                   // [4,220,16,32,220] f32

    prepass_kernel<<<BB * HH / 2, 512>>>(inputs);
    conv_main_kernel<<<BB * HO * 2, 256>>>(kernel, out);
}